// round 13
// baseline (speedup 1.0000x reference)
#include <cuda_runtime.h>
#include <cstdint>

#define FEAT            128
#define WARPS_PER_BLOCK 8
#define BLOCK_THREADS   256

#define STAGE_ROWS   16
#define STAGE_BYTES  (STAGE_ROWS * FEAT * 4)   // 8192
#define DEPTH        3

// Dynamic SMEM: [0, 8*DEPTH*8) mbarriers; buffers from 1024.
#define SMEM_BUF_BASE 1024
#define SMEM_TOTAL    (SMEM_BUF_BASE + WARPS_PER_BLOCK * DEPTH * STAGE_BYTES)

// ---------------------------------------------------------------------------
// PDL + PTX helpers
// ---------------------------------------------------------------------------
__device__ __forceinline__ void pdl_trigger() {
    asm volatile("griddepcontrol.launch_dependents;" ::: "memory");
}
__device__ __forceinline__ void pdl_wait() {
    asm volatile("griddepcontrol.wait;" ::: "memory");
}
__device__ __forceinline__ uint32_t smem_u32(const void* p) {
    uint32_t a;
    asm("{ .reg .u64 t; cvta.to.shared.u64 t, %1; cvt.u32.u64 %0, t; }"
        : "=r"(a) : "l"(p));
    return a;
}
__device__ __forceinline__ void mbar_init(uint32_t addr, uint32_t count) {
    asm volatile("mbarrier.init.shared.b64 [%0], %1;" :: "r"(addr), "r"(count)
                 : "memory");
}
__device__ __forceinline__ void mbar_wait(uint32_t addr, uint32_t phase) {
    uint32_t done = 0;
    while (!done) {
        asm volatile(
            "{ .reg .pred p;\n\t"
            "mbarrier.try_wait.parity.acquire.cta.shared::cta.b64 p, [%1], %2, 0x989680;\n\t"
            "selp.b32 %0, 1, 0, p; }"
            : "=r"(done) : "r"(addr), "r"(phase) : "memory");
    }
}
__device__ __forceinline__ void tma_bulk_1d(uint32_t dst_smem,
                                            const void* src_gmem,
                                            uint32_t bytes, uint32_t bar) {
    asm volatile("mbarrier.arrive.expect_tx.shared.b64 _, [%0], %1;"
                 :: "r"(bar), "r"(bytes) : "memory");
    asm volatile(
        "cp.async.bulk.shared::cta.global.mbarrier::complete_tx::bytes "
        "[%0], [%1], %2, [%3];"
        :: "r"(dst_smem), "l"(src_gmem), "r"(bytes), "r"(bar) : "memory");
}

// ---------------------------------------------------------------------------
// Kernel 1 (prologue): zero the output, then signal dependents (PDL).
// ---------------------------------------------------------------------------
__global__ void prologue_kernel(float4* __restrict__ out, int n4) {
    int i = blockIdx.x * blockDim.x + threadIdx.x;
    if (i < n4) out[i] = make_float4(0.f, 0.f, 0.f, 0.f);
    pdl_trigger();
}

// ---------------------------------------------------------------------------
// Kernel 2: persistent, balanced, TMA-streamed sorted segment sum.
// Grid = one CTA per SM (single wave). The row range [0, n_rows) is split
// evenly over all warps (diff <= 1 row). Each warp streams its span through
// a private DEPTH=3 x 8KB SMEM ring via cp.async.bulk + mbarrier — the
// pipeline never restarts (no waves, no chunk boundaries). Each lane owns 4
// features; sortedness fast path + lazy-PDL atomic flush as in the champion.
// ---------------------------------------------------------------------------
__device__ __forceinline__ void flush_acc(float* __restrict__ out,
                                          int seg, int lane, const float4& acc,
                                          int max_seg, bool& synced) {
    if (!synced) { pdl_wait(); synced = true; }
    if (seg < 0 || seg >= max_seg) return;
    float* p = out + (size_t)seg * FEAT + lane * 4;
    atomicAdd(p + 0, acc.x);
    atomicAdd(p + 1, acc.y);
    atomicAdd(p + 2, acc.z);
    atomicAdd(p + 3, acc.w);
}

#define ACC_ROW(S, V)                                                         \
    do {                                                                      \
        if ((S) != cur) {                                                     \
            flush_acc(out, cur, lane, acc, max_seg, synced);                  \
            cur = (S);                                                        \
            acc = make_float4(0.f, 0.f, 0.f, 0.f);                            \
        }                                                                     \
        acc.x += (V).x; acc.y += (V).y; acc.z += (V).z; acc.w += (V).w;       \
    } while (0)

__global__ __launch_bounds__(BLOCK_THREADS, 1)
void seg_sum_kernel(const char* __restrict__ hbytes,  // h_t as bytes
                    const int* __restrict__ braw,     // batch
                    float* __restrict__ out,          // [max_seg][FEAT]
                    int n_rows, int max_seg, int total_warps) {
    extern __shared__ char smem[];
    const int wid     = threadIdx.x >> 5;
    const int lane    = threadIdx.x & 31;
    const int warp_id = blockIdx.x * WARPS_PER_BLOCK + wid;

    // dtype detect (little-endian int64 < 2^31 has zero high-halves at odd words)
    int didx = n_rows - 1 - 2 * lane;
    if (!(didx & 1)) didx -= 1;
    int nz = (didx > 0) ? (braw[didx] != 0) : 0;
    const int stride = __any_sync(0xFFFFFFFF, nz) ? 1 : 2;

    // Balanced split: first `rem` warps get q+1 rows.
    const int q   = n_rows / total_warps;
    const int rem = n_rows - q * total_warps;
    int start, cnt;
    if (warp_id < rem) { cnt = q + 1; start = warp_id * (q + 1); }
    else               { cnt = q;     start = warp_id * q + rem; }
    if (cnt <= 0) return;
    const int end     = start + cnt;
    const int nstages = (cnt + STAGE_ROWS - 1) / STAGE_ROWS;

    const uint32_t bar0 = smem_u32(smem) + wid * DEPTH * 8;
    const char*    buf0 = smem + SMEM_BUF_BASE + wid * DEPTH * STAGE_BYTES;
    const uint32_t buf0_sa = smem_u32(buf0);

    if (lane == 0) {
        #pragma unroll
        for (int d = 0; d < DEPTH; ++d) mbar_init(bar0 + d * 8, 1);
        asm volatile("fence.proxy.async.shared::cta;" ::: "memory");
    }
    __syncwarp();

    // Prime the ring.
    if (lane == 0) {
        int np = min(DEPTH, nstages);
        for (int s = 0; s < np; ++s) {
            int rbase = start + s * STAGE_ROWS;
            uint32_t bytes = (uint32_t)min(STAGE_ROWS, end - rbase) * FEAT * 4;
            tma_bulk_1d(buf0_sa + s * STAGE_BYTES,
                        hbytes + (size_t)rbase * FEAT * 4, bytes,
                        bar0 + s * 8);
        }
    }
    __syncwarp();

    bool synced = false;
    float4 acc = make_float4(0.f, 0.f, 0.f, 0.f);
    int cur = braw[start * stride];

    for (int s = 0; s < nstages; ++s) {
        const int slot = s % DEPTH;
        mbar_wait(bar0 + slot * 8, (s / DEPTH) & 1);

        const int rbase = start + s * STAGE_ROWS;
        const int rows  = min(STAGE_ROWS, end - rbase);
        const float4* bp =
            (const float4*)(buf0 + slot * STAGE_BYTES) + lane;  // +32 per row

        if (rows == STAGE_ROWS) {
            #pragma unroll
            for (int grp = 0; grp < 2; ++grp) {
                int r0 = rbase + grp * 8;
                int s7 = braw[(r0 + 7) * stride];
                float4 v[8];
                #pragma unroll
                for (int j = 0; j < 8; ++j) v[j] = bp[(grp * 8 + j) * 32];

                if (s7 == cur) {
                    float4 t01, t23, t45, t67, t03, t47, t;
                    t01.x = v[0].x + v[1].x; t01.y = v[0].y + v[1].y; t01.z = v[0].z + v[1].z; t01.w = v[0].w + v[1].w;
                    t23.x = v[2].x + v[3].x; t23.y = v[2].y + v[3].y; t23.z = v[2].z + v[3].z; t23.w = v[2].w + v[3].w;
                    t45.x = v[4].x + v[5].x; t45.y = v[4].y + v[5].y; t45.z = v[4].z + v[5].z; t45.w = v[4].w + v[5].w;
                    t67.x = v[6].x + v[7].x; t67.y = v[6].y + v[7].y; t67.z = v[6].z + v[7].z; t67.w = v[6].w + v[7].w;
                    t03.x = t01.x + t23.x; t03.y = t01.y + t23.y; t03.z = t01.z + t23.z; t03.w = t01.w + t23.w;
                    t47.x = t45.x + t67.x; t47.y = t45.y + t67.y; t47.z = t45.z + t67.z; t47.w = t45.w + t67.w;
                    t.x = t03.x + t47.x; t.y = t03.y + t47.y; t.z = t03.z + t47.z; t.w = t03.w + t47.w;
                    acc.x += t.x; acc.y += t.y; acc.z += t.z; acc.w += t.w;
                } else {
                    #pragma unroll
                    for (int j = 0; j < 8; ++j) {
                        int sg = braw[(r0 + j) * stride];
                        ACC_ROW(sg, v[j]);
                    }
                }
            }
        } else {
            for (int j = 0; j < rows; ++j) {
                int sg = braw[(rbase + j) * stride];
                float4 vv = bp[j * 32];
                ACC_ROW(sg, vv);
            }
        }

        // Reads of this slot done -> refill with stage s+DEPTH.
        __syncwarp();
        if (lane == 0 && s + DEPTH < nstages) {
            int nb = start + (s + DEPTH) * STAGE_ROWS;
            uint32_t bytes = (uint32_t)min(STAGE_ROWS, end - nb) * FEAT * 4;
            tma_bulk_1d(buf0_sa + slot * STAGE_BYTES,
                        hbytes + (size_t)nb * FEAT * 4, bytes,
                        bar0 + slot * 8);
        }
        __syncwarp();
    }
    flush_acc(out, cur, lane, acc, max_seg, synced);
}

// ---------------------------------------------------------------------------
// Launch. Inputs: h_t (float32, N*FEAT) and batch (int32 or int64, N).
// Order disambiguated by element count (h_t is FEAT x larger).
// Persistent grid: one CTA per SM (queried at launch; deterministic).
// ---------------------------------------------------------------------------
extern "C" void kernel_launch(void* const* d_in, const int* in_sizes, int n_in,
                              void* d_out, int out_size) {
    int hi = 0, bi = 1;
    if (n_in >= 2 && in_sizes[0] < in_sizes[1]) { hi = 1; bi = 0; }

    const char* hbytes   = (const char*)d_in[hi];
    const int*  batchRaw = (const int*)d_in[bi];
    float*      out      = (float*)d_out;

    const int n_rows  = in_sizes[bi];
    const int max_seg = out_size / FEAT;

    // 1) zero output (PDL trigger at end)
    int n4 = out_size / 4;
    prologue_kernel<<<(n4 + 255) / 256, 256>>>((float4*)d_out, n4);

    // 2) persistent TMA-streamed segment sum — single wave, PDL launch
    int num_sms = 148;
    cudaDeviceGetAttribute(&num_sms, cudaDevAttrMultiProcessorCount, 0);
    const int n_blocks    = num_sms;
    const int total_warps = n_blocks * WARPS_PER_BLOCK;

    cudaFuncSetAttribute(seg_sum_kernel,
                         cudaFuncAttributeMaxDynamicSharedMemorySize,
                         SMEM_TOTAL);

    cudaLaunchConfig_t cfg = {};
    cfg.gridDim  = dim3(n_blocks, 1, 1);
    cfg.blockDim = dim3(BLOCK_THREADS, 1, 1);
    cfg.dynamicSmemBytes = SMEM_TOTAL;
    cfg.stream = 0;
    cudaLaunchAttribute attrs[1];
    attrs[0].id = cudaLaunchAttributeProgrammaticStreamSerialization;
    attrs[0].val.programmaticStreamSerializationAllowed = 1;
    cfg.attrs = attrs;
    cfg.numAttrs = 1;
    cudaLaunchKernelEx(&cfg, seg_sum_kernel, hbytes, batchRaw, out,
                       n_rows, max_seg, total_warps);
}

// round 14
// speedup vs baseline: 1.0394x; 1.0394x over previous
#include <cuda_runtime.h>
#include <cstdint>

#define FEAT            128
#define ROWS_PER_WARP   256
#define WARPS_PER_BLOCK 4
#define BLOCK_THREADS   128
#define CTAS_PER_SM     2

#define STAGE_ROWS   16
#define STAGE_BYTES  (STAGE_ROWS * FEAT * 4)   // 8192
#define DEPTH        3

// Dynamic SMEM: [0, WARPS*DEPTH*8) mbarriers; buffers from 1024.
#define SMEM_BUF_BASE 1024
#define SMEM_TOTAL    (SMEM_BUF_BASE + WARPS_PER_BLOCK * DEPTH * STAGE_BYTES)  // 99328

// ---------------------------------------------------------------------------
// PDL + PTX helpers
// ---------------------------------------------------------------------------
__device__ __forceinline__ void pdl_trigger() {
    asm volatile("griddepcontrol.launch_dependents;" ::: "memory");
}
__device__ __forceinline__ void pdl_wait() {
    asm volatile("griddepcontrol.wait;" ::: "memory");
}
__device__ __forceinline__ uint32_t smem_u32(const void* p) {
    uint32_t a;
    asm("{ .reg .u64 t; cvta.to.shared.u64 t, %1; cvt.u32.u64 %0, t; }"
        : "=r"(a) : "l"(p));
    return a;
}
__device__ __forceinline__ void mbar_init(uint32_t addr, uint32_t count) {
    asm volatile("mbarrier.init.shared.b64 [%0], %1;" :: "r"(addr), "r"(count)
                 : "memory");
}
__device__ __forceinline__ void mbar_wait(uint32_t addr, uint32_t phase) {
    uint32_t done = 0;
    while (!done) {
        asm volatile(
            "{ .reg .pred p;\n\t"
            "mbarrier.try_wait.parity.acquire.cta.shared::cta.b64 p, [%1], %2, 0x989680;\n\t"
            "selp.b32 %0, 1, 0, p; }"
            : "=r"(done) : "r"(addr), "r"(phase) : "memory");
    }
}
__device__ __forceinline__ void tma_bulk_1d(uint32_t dst_smem,
                                            const void* src_gmem,
                                            uint32_t bytes, uint32_t bar) {
    asm volatile("mbarrier.arrive.expect_tx.shared.b64 _, [%0], %1;"
                 :: "r"(bar), "r"(bytes) : "memory");
    asm volatile(
        "cp.async.bulk.shared::cta.global.mbarrier::complete_tx::bytes "
        "[%0], [%1], %2, [%3];"
        :: "r"(dst_smem), "l"(src_gmem), "r"(bytes), "r"(bar) : "memory");
}

// ---------------------------------------------------------------------------
// Kernel 1 (prologue): zero the output, then signal dependents (PDL).
// ---------------------------------------------------------------------------
__global__ void prologue_kernel(float4* __restrict__ out, int n4) {
    int i = blockIdx.x * blockDim.x + threadIdx.x;
    if (i < n4) out[i] = make_float4(0.f, 0.f, 0.f, 0.f);
    pdl_trigger();
}

// ---------------------------------------------------------------------------
// Kernel 2: TMA-streamed sorted segment sum, 2 CTAs/SM for stagger.
// One warp owns ROWS_PER_WARP contiguous rows, streamed as 16-row (8KB)
// stages through a private DEPTH=3 ring (cp.async.bulk + mbarrier). Small
// CTAs (4 warps, 97KB smem) let two CTAs co-reside per SM: one CTA's drain /
// prime phases are hidden behind the other's steady-state streaming. Each
// lane owns 4 features; sortedness fast path + lazy-PDL atomic flush as in
// the champion design.
// ---------------------------------------------------------------------------
__device__ __forceinline__ void flush_acc(float* __restrict__ out,
                                          int seg, int lane, const float4& acc,
                                          int max_seg, bool& synced) {
    if (!synced) { pdl_wait(); synced = true; }
    if (seg < 0 || seg >= max_seg) return;
    float* p = out + (size_t)seg * FEAT + lane * 4;
    atomicAdd(p + 0, acc.x);
    atomicAdd(p + 1, acc.y);
    atomicAdd(p + 2, acc.z);
    atomicAdd(p + 3, acc.w);
}

#define ACC_ROW(S, V)                                                         \
    do {                                                                      \
        if ((S) != cur) {                                                     \
            flush_acc(out, cur, lane, acc, max_seg, synced);                  \
            cur = (S);                                                        \
            acc = make_float4(0.f, 0.f, 0.f, 0.f);                            \
        }                                                                     \
        acc.x += (V).x; acc.y += (V).y; acc.z += (V).z; acc.w += (V).w;       \
    } while (0)

__global__ __launch_bounds__(BLOCK_THREADS, CTAS_PER_SM)
void seg_sum_kernel(const char* __restrict__ hbytes,  // h_t as bytes
                    const int* __restrict__ braw,     // batch
                    float* __restrict__ out,          // [max_seg][FEAT]
                    int n_rows, int max_seg) {
    extern __shared__ char smem[];
    const int wid     = threadIdx.x >> 5;
    const int lane    = threadIdx.x & 31;
    const int warp_id = blockIdx.x * WARPS_PER_BLOCK + wid;

    // dtype detect (little-endian int64 < 2^31 has zero high-halves at odd words)
    int didx = n_rows - 1 - 2 * lane;
    if (!(didx & 1)) didx -= 1;
    int nz = (didx > 0) ? (braw[didx] != 0) : 0;
    const int stride = __any_sync(0xFFFFFFFF, nz) ? 1 : 2;

    const uint32_t bar0 = smem_u32(smem) + wid * DEPTH * 8;
    const char*    buf0 = smem + SMEM_BUF_BASE + wid * DEPTH * STAGE_BYTES;
    const uint32_t buf0_sa = smem_u32(buf0);

    int start = warp_id * ROWS_PER_WARP;
    if (start >= n_rows) return;
    const int end     = min(start + ROWS_PER_WARP, n_rows);
    const int cnt     = end - start;
    const int nstages = (cnt + STAGE_ROWS - 1) / STAGE_ROWS;

    if (lane == 0) {
        #pragma unroll
        for (int d = 0; d < DEPTH; ++d) mbar_init(bar0 + d * 8, 1);
        asm volatile("fence.proxy.async.shared::cta;" ::: "memory");
    }
    __syncwarp();

    // Prime the ring.
    if (lane == 0) {
        int np = min(DEPTH, nstages);
        for (int s = 0; s < np; ++s) {
            int rbase = start + s * STAGE_ROWS;
            uint32_t bytes = (uint32_t)min(STAGE_ROWS, end - rbase) * FEAT * 4;
            tma_bulk_1d(buf0_sa + s * STAGE_BYTES,
                        hbytes + (size_t)rbase * FEAT * 4, bytes,
                        bar0 + s * 8);
        }
    }
    __syncwarp();

    bool synced = false;
    float4 acc = make_float4(0.f, 0.f, 0.f, 0.f);
    int cur = braw[start * stride];

    for (int s = 0; s < nstages; ++s) {
        const int slot = s % DEPTH;
        mbar_wait(bar0 + slot * 8, (s / DEPTH) & 1);

        const int rbase = start + s * STAGE_ROWS;
        const int rows  = min(STAGE_ROWS, end - rbase);
        const float4* bp =
            (const float4*)(buf0 + slot * STAGE_BYTES) + lane;  // +32 per row

        if (rows == STAGE_ROWS) {
            #pragma unroll
            for (int grp = 0; grp < 2; ++grp) {
                int r0 = rbase + grp * 8;
                int s7 = braw[(r0 + 7) * stride];
                float4 v[8];
                #pragma unroll
                for (int j = 0; j < 8; ++j) v[j] = bp[(grp * 8 + j) * 32];

                if (s7 == cur) {
                    float4 t01, t23, t45, t67, t03, t47, t;
                    t01.x = v[0].x + v[1].x; t01.y = v[0].y + v[1].y; t01.z = v[0].z + v[1].z; t01.w = v[0].w + v[1].w;
                    t23.x = v[2].x + v[3].x; t23.y = v[2].y + v[3].y; t23.z = v[2].z + v[3].z; t23.w = v[2].w + v[3].w;
                    t45.x = v[4].x + v[5].x; t45.y = v[4].y + v[5].y; t45.z = v[4].z + v[5].z; t45.w = v[4].w + v[5].w;
                    t67.x = v[6].x + v[7].x; t67.y = v[6].y + v[7].y; t67.z = v[6].z + v[7].z; t67.w = v[6].w + v[7].w;
                    t03.x = t01.x + t23.x; t03.y = t01.y + t23.y; t03.z = t01.z + t23.z; t03.w = t01.w + t23.w;
                    t47.x = t45.x + t67.x; t47.y = t45.y + t67.y; t47.z = t45.z + t67.z; t47.w = t45.w + t67.w;
                    t.x = t03.x + t47.x; t.y = t03.y + t47.y; t.z = t03.z + t47.z; t.w = t03.w + t47.w;
                    acc.x += t.x; acc.y += t.y; acc.z += t.z; acc.w += t.w;
                } else {
                    #pragma unroll
                    for (int j = 0; j < 8; ++j) {
                        int sg = braw[(r0 + j) * stride];
                        ACC_ROW(sg, v[j]);
                    }
                }
            }
        } else {
            for (int j = 0; j < rows; ++j) {
                int sg = braw[(rbase + j) * stride];
                float4 vv = bp[j * 32];
                ACC_ROW(sg, vv);
            }
        }

        // Reads of this slot done -> refill with stage s+DEPTH.
        __syncwarp();
        if (lane == 0 && s + DEPTH < nstages) {
            int nb = start + (s + DEPTH) * STAGE_ROWS;
            uint32_t bytes = (uint32_t)min(STAGE_ROWS, end - nb) * FEAT * 4;
            tma_bulk_1d(buf0_sa + slot * STAGE_BYTES,
                        hbytes + (size_t)nb * FEAT * 4, bytes,
                        bar0 + slot * 8);
        }
        __syncwarp();
    }
    flush_acc(out, cur, lane, acc, max_seg, synced);
}

// ---------------------------------------------------------------------------
// Launch. Inputs: h_t (float32, N*FEAT) and batch (int32 or int64, N).
// Order disambiguated by element count (h_t is FEAT x larger).
// ---------------------------------------------------------------------------
extern "C" void kernel_launch(void* const* d_in, const int* in_sizes, int n_in,
                              void* d_out, int out_size) {
    int hi = 0, bi = 1;
    if (n_in >= 2 && in_sizes[0] < in_sizes[1]) { hi = 1; bi = 0; }

    const char* hbytes   = (const char*)d_in[hi];
    const int*  batchRaw = (const int*)d_in[bi];
    float*      out      = (float*)d_out;

    const int n_rows  = in_sizes[bi];
    const int max_seg = out_size / FEAT;

    // 1) zero output (PDL trigger at end)
    int n4 = out_size / 4;
    prologue_kernel<<<(n4 + 255) / 256, 256>>>((float4*)d_out, n4);

    // 2) TMA-streamed segment sum — small CTAs, 2/SM, PDL launch
    int n_warps  = (n_rows + ROWS_PER_WARP - 1) / ROWS_PER_WARP;
    int n_blocks = (n_warps + WARPS_PER_BLOCK - 1) / WARPS_PER_BLOCK;

    cudaFuncSetAttribute(seg_sum_kernel,
                         cudaFuncAttributeMaxDynamicSharedMemorySize,
                         SMEM_TOTAL);

    cudaLaunchConfig_t cfg = {};
    cfg.gridDim  = dim3(n_blocks, 1, 1);
    cfg.blockDim = dim3(BLOCK_THREADS, 1, 1);
    cfg.dynamicSmemBytes = SMEM_TOTAL;
    cfg.stream = 0;
    cudaLaunchAttribute attrs[1];
    attrs[0].id = cudaLaunchAttributeProgrammaticStreamSerialization;
    attrs[0].val.programmaticStreamSerializationAllowed = 1;
    cfg.attrs = attrs;
    cfg.numAttrs = 1;
    cudaLaunchKernelEx(&cfg, seg_sum_kernel, hbytes, batchRaw, out,
                       n_rows, max_seg);
}

// round 15
// speedup vs baseline: 1.1375x; 1.0944x over previous
#include <cuda_runtime.h>
#include <cstdint>

// Problem constants (match reference setup_inputs)
#define FEAT        128

// Tuning (champion shape: MLP 8/warp, ~40 warps/SM)
#define ROWS_PER_WARP   128
#define WARPS_PER_BLOCK 8
#define BLOCK_THREADS   (WARPS_PER_BLOCK * 32)

// ---------------------------------------------------------------------------
// PDL primitives
// ---------------------------------------------------------------------------
__device__ __forceinline__ void pdl_trigger() {
    asm volatile("griddepcontrol.launch_dependents;" ::: "memory");
}
__device__ __forceinline__ void pdl_wait() {
    asm volatile("griddepcontrol.wait;" ::: "memory");
}

// ---------------------------------------------------------------------------
// Kernel 1 (prologue): zero the output, then signal dependents (PDL).
// ---------------------------------------------------------------------------
__global__ void prologue_kernel(float4* __restrict__ out, int n4) {
    int i = blockIdx.x * blockDim.x + threadIdx.x;
    if (i < n4) out[i] = make_float4(0.f, 0.f, 0.f, 0.f);
    pdl_trigger();
}

// ---------------------------------------------------------------------------
// Kernel 2: sorted segment sum (champion design).
// One warp owns ROWS_PER_WARP contiguous rows; each lane owns 4 features
// (one LDG.128 per row per lane, streaming/evict-first). Sortedness
// shortcut: per 8-row group load only the LAST id; equality with cur implies
// the whole group belongs to one segment -> branch-free tree accumulation.
// atomicAdd flush on segment change / chunk end (chunks can split a segment
// across warps). pdl_wait() is issued lazily before the FIRST flush so the
// 512MB load stream overlaps the prologue's zeroing.
// Dtype detect (int32 vs int64 batch) inline per warp: odd int32 words of
// little-endian int64 (< 2^31) are zero high-halves.
// ---------------------------------------------------------------------------
__device__ __forceinline__ void flush_acc(float* __restrict__ out,
                                          int seg, int lane, const float4& acc,
                                          int max_seg, bool& synced) {
    if (!synced) { pdl_wait(); synced = true; }
    if (seg < 0 || seg >= max_seg) return;  // insurance against bad ids
    float* p = out + (size_t)seg * FEAT + lane * 4;
    atomicAdd(p + 0, acc.x);
    atomicAdd(p + 1, acc.y);
    atomicAdd(p + 2, acc.z);
    atomicAdd(p + 3, acc.w);
}

__global__ __launch_bounds__(BLOCK_THREADS)
void seg_sum_kernel(const float4* __restrict__ h,     // [n_rows][32] float4
                    const int* __restrict__ braw,     // batch, stride words
                    float* __restrict__ out,          // [max_seg][FEAT]
                    int n_rows, int max_seg) {
    const int warp_id = blockIdx.x * WARPS_PER_BLOCK + (threadIdx.x >> 5);
    const int lane    = threadIdx.x & 31;

    // Inline dtype detect (warp-wide ballot over odd tail words).
    int didx = n_rows - 1 - 2 * lane;
    if (!(didx & 1)) didx -= 1;                       // force odd index
    int nz = (didx > 0) ? (braw[didx] != 0) : 0;
    const int stride = __any_sync(0xFFFFFFFF, nz) ? 1 : 2;

    int start = warp_id * ROWS_PER_WARP;
    if (start >= n_rows) return;
    int end = min(start + ROWS_PER_WARP, n_rows);

    bool synced = false;
    float4 acc = make_float4(0.f, 0.f, 0.f, 0.f);
    int cur = braw[start * stride];

    int r = start;
    for (; r + 8 <= end; r += 8) {
        // One warp-uniform index load per 8 rows (sorted => s7==cur covers all)
        int s7 = braw[(r + 7) * stride];

        float4 v[8];
        #pragma unroll
        for (int j = 0; j < 8; ++j)
            v[j] = __ldcs(&h[(size_t)(r + j) * 32 + lane]);

        if (s7 == cur) {
            // Fast path: tree-sum the 8 rows, single dependency on acc.
            float4 t01, t23, t45, t67, t03, t47, t;
            t01.x = v[0].x + v[1].x; t01.y = v[0].y + v[1].y; t01.z = v[0].z + v[1].z; t01.w = v[0].w + v[1].w;
            t23.x = v[2].x + v[3].x; t23.y = v[2].y + v[3].y; t23.z = v[2].z + v[3].z; t23.w = v[2].w + v[3].w;
            t45.x = v[4].x + v[5].x; t45.y = v[4].y + v[5].y; t45.z = v[4].z + v[5].z; t45.w = v[4].w + v[5].w;
            t67.x = v[6].x + v[7].x; t67.y = v[6].y + v[7].y; t67.z = v[6].z + v[7].z; t67.w = v[6].w + v[7].w;
            t03.x = t01.x + t23.x; t03.y = t01.y + t23.y; t03.z = t01.z + t23.z; t03.w = t01.w + t23.w;
            t47.x = t45.x + t67.x; t47.y = t45.y + t67.y; t47.z = t45.z + t67.z; t47.w = t45.w + t67.w;
            t.x = t03.x + t47.x; t.y = t03.y + t47.y; t.z = t03.z + t47.z; t.w = t03.w + t47.w;
            acc.x += t.x; acc.y += t.y; acc.z += t.z; acc.w += t.w;
        } else {
            // Slow path (segment boundary inside this group): per-row logic.
            #pragma unroll
            for (int j = 0; j < 8; ++j) {
                int s = braw[(r + j) * stride];
                if (s != cur) {
                    flush_acc(out, cur, lane, acc, max_seg, synced);
                    cur = s;
                    acc = make_float4(0.f, 0.f, 0.f, 0.f);
                }
                acc.x += v[j].x; acc.y += v[j].y; acc.z += v[j].z; acc.w += v[j].w;
            }
        }
    }
    // Tail (< 8 rows)
    for (; r < end; ++r) {
        int s = braw[r * stride];
        float4 vv = __ldcs(&h[(size_t)r * 32 + lane]);
        if (s != cur) {
            flush_acc(out, cur, lane, acc, max_seg, synced);
            cur = s;
            acc = make_float4(0.f, 0.f, 0.f, 0.f);
        }
        acc.x += vv.x; acc.y += vv.y; acc.z += vv.z; acc.w += vv.w;
    }
    // Final flush
    flush_acc(out, cur, lane, acc, max_seg, synced);
}

// ---------------------------------------------------------------------------
// Launch. Inputs: h_t (float32, N*FEAT) and batch (int32 or int64, N).
// Order disambiguated by element count (h_t is FEAT x larger).
// seg_sum is launched with programmatic stream serialization (PDL) so it
// overlaps the prologue's zeroing.
// ---------------------------------------------------------------------------
extern "C" void kernel_launch(void* const* d_in, const int* in_sizes, int n_in,
                              void* d_out, int out_size) {
    int hi = 0, bi = 1;
    if (n_in >= 2 && in_sizes[0] < in_sizes[1]) { hi = 1; bi = 0; }

    const float4* h        = (const float4*)d_in[hi];
    const int*    batchRaw = (const int*)d_in[bi];
    float*        out      = (float*)d_out;

    const int n_rows  = in_sizes[bi];
    const int max_seg = out_size / FEAT;

    // 1) zero output (signals PDL completion when done)
    int n4 = out_size / 4;
    prologue_kernel<<<(n4 + 255) / 256, 256>>>((float4*)d_out, n4);

    // 2) segment sum — PDL launch, overlaps with prologue
    int n_warps  = (n_rows + ROWS_PER_WARP - 1) / ROWS_PER_WARP;
    int n_blocks = (n_warps + WARPS_PER_BLOCK - 1) / WARPS_PER_BLOCK;

    cudaLaunchConfig_t cfg = {};
    cfg.gridDim  = dim3(n_blocks, 1, 1);
    cfg.blockDim = dim3(BLOCK_THREADS, 1, 1);
    cfg.dynamicSmemBytes = 0;
    cfg.stream = 0;  // legacy default stream (same as <<<>>> above)
    cudaLaunchAttribute attrs[1];
    attrs[0].id = cudaLaunchAttributeProgrammaticStreamSerialization;
    attrs[0].val.programmaticStreamSerializationAllowed = 1;
    cfg.attrs = attrs;
    cfg.numAttrs = 1;
    cudaLaunchKernelEx(&cfg, seg_sum_kernel, h, batchRaw, out, n_rows, max_seg);
}